// round 3
// baseline (speedup 1.0000x reference)
#include <cuda_runtime.h>
#include <cuda_bf16.h>
#include <math.h>

// ---------------- problem constants ----------------
#define BB 2
#define SS 2048
#define DIM 1024
#define HEADS 16
#define HEAD_DIM 64
#define FFN 4096
#define TOK (BB * SS)   // 4096 tokens

// ---------------- scratch (device globals; no allocations allowed) ----------
__device__ float g_h[TOK * DIM];          // LN output (reused for ln1 and ln2)
__device__ float g_q[TOK * DIM];
__device__ float g_k[TOK * DIM];
__device__ float g_v[TOK * DIM];
__device__ float g_attn[TOK * DIM];
__device__ float g_x1[TOK * DIM];         // x + attn @ wo
__device__ float g_m[TOK * FFN];          // gelu(h @ w1)
__device__ float g_scores[(long long)BB * HEADS * SS * SS];  // 536 MB

// ---------------- LayerNorm: one block per row of 1024 ----------------
__global__ __launch_bounds__(256)
void ln_kernel(const float* __restrict__ X, const float* __restrict__ W,
               const float* __restrict__ Bv, float* __restrict__ Y)
{
    long row = blockIdx.x;
    const float* x = X + row * DIM;
    __shared__ float sm[DIM];
    __shared__ float red[256];
    int tid = threadIdx.x;

    float s = 0.f;
    for (int i = tid; i < DIM; i += 256) { float v = x[i]; sm[i] = v; s += v; }
    red[tid] = s; __syncthreads();
    for (int o = 128; o > 0; o >>= 1) { if (tid < o) red[tid] += red[tid + o]; __syncthreads(); }
    float mean = red[0] * (1.0f / DIM);
    __syncthreads();

    float s2 = 0.f;
    for (int i = tid; i < DIM; i += 256) { float d = sm[i] - mean; s2 += d * d; }
    red[tid] = s2; __syncthreads();
    for (int o = 128; o > 0; o >>= 1) { if (tid < o) red[tid] += red[tid + o]; __syncthreads(); }
    float var = red[0] * (1.0f / DIM);
    float inv = rsqrtf(var + 1e-12f);

    float* y = Y + row * DIM;
    for (int i = tid; i < DIM; i += 256)
        y[i] = W[i] * ((sm[i] - mean) * inv) + Bv[i];
}

// ---------------- Softmax (in place) over rows of length SS, with mask ------
__global__ __launch_bounds__(256)
void softmax_kernel(float* __restrict__ P, const float* __restrict__ mask)
{
    long row = blockIdx.x;                 // 0 .. B*H*S-1
    int srow = (int)(row % SS);            // query position for mask broadcast
    float* p = P + row * (long)SS;
    const float* mrow = mask + (long)srow * SS;
    __shared__ float sm[SS];
    __shared__ float red[256];
    int tid = threadIdx.x;

    float mx = -INFINITY;
    for (int i = tid; i < SS; i += 256) {
        float v = p[i] + mrow[i];
        sm[i] = v;
        mx = fmaxf(mx, v);
    }
    red[tid] = mx; __syncthreads();
    for (int o = 128; o > 0; o >>= 1) { if (tid < o) red[tid] = fmaxf(red[tid], red[tid + o]); __syncthreads(); }
    mx = red[0]; __syncthreads();

    float s = 0.f;
    for (int i = tid; i < SS; i += 256) {
        float e = __expf(sm[i] - mx);
        sm[i] = e;
        s += e;
    }
    red[tid] = s; __syncthreads();
    for (int o = 128; o > 0; o >>= 1) { if (tid < o) red[tid] += red[tid + o]; __syncthreads(); }
    float inv = 1.0f / red[0];

    for (int i = tid; i < SS; i += 256) p[i] = sm[i] * inv;
}

// ---------------- Tiled SGEMM 128x128x8, 256 threads, 8x8 microtile ---------
// C[m,n] = epi( alpha * sum_k A(m,k)*B(k,n) )
//   A(m,k) = A[m*lda + k]
//   B(k,n) = TB ? B[n*ldb + k] : B[k*ldb + n]
// Batched over blockIdx.z: offset = (z/Hb)*bs* + (z%Hb)*hs*
// EPI: 0 = alpha*acc ; 1 = alpha*acc + RES[m*ldc+n] ; 2 = gelu_exact(acc)
template<int EPI, bool TB>
__global__ __launch_bounds__(256)
void gemm_kernel(const float* __restrict__ A, const float* __restrict__ B,
                 float* __restrict__ C, const float* __restrict__ RES,
                 int M, int N, int K, int lda, int ldb, int ldc,
                 int Hb,
                 long bsA, long hsA, long bsB, long hsB, long bsC, long hsC,
                 float alpha)
{
    int z = blockIdx.z;
    int zb = z / Hb, zh = z % Hb;
    A += zb * bsA + zh * hsA;
    B += zb * bsB + zh * hsB;
    C += zb * bsC + zh * hsC;
    if (EPI == 1) RES += zb * bsC + zh * hsC;   // residual shares C layout

    __shared__ float As[8][132];
    __shared__ float Bs[8][132];

    const int m0 = blockIdx.y * 128;
    const int n0 = blockIdx.x * 128;
    const int tid = threadIdx.x;
    const int tx = tid & 15;        // 0..15  -> cols tx*8 .. tx*8+7
    const int ty = tid >> 4;        // 0..15  -> rows ty*8 .. ty*8+7

    float acc[8][8] = {};

    for (int k0 = 0; k0 < K; k0 += 8) {
        // --- load A tile (128 rows x 8 k) transposed into As[k][m]
        #pragma unroll
        for (int it = 0; it < 4; it++) {
            int idx = tid + it * 256;
            int m = idx >> 3, k = idx & 7;
            int gm = m0 + m, gk = k0 + k;
            float v = 0.f;
            if (gm < M && gk < K) v = A[(long)gm * lda + gk];
            As[k][m] = v;
        }
        // --- load B tile into Bs[k][n]
        #pragma unroll
        for (int it = 0; it < 4; it++) {
            int idx = tid + it * 256;
            if (!TB) {
                int k = idx >> 7, n = idx & 127;
                int gk = k0 + k, gn = n0 + n;
                float v = 0.f;
                if (gk < K && gn < N) v = B[(long)gk * ldb + gn];
                Bs[k][n] = v;
            } else {
                int n = idx >> 3, k = idx & 7;
                int gk = k0 + k, gn = n0 + n;
                float v = 0.f;
                if (gk < K && gn < N) v = B[(long)gn * ldb + gk];
                Bs[k][n] = v;
            }
        }
        __syncthreads();

        #pragma unroll
        for (int k = 0; k < 8; k++) {
            float a[8], b[8];
            *(float4*)&a[0] = *(const float4*)&As[k][ty * 8];
            *(float4*)&a[4] = *(const float4*)&As[k][ty * 8 + 4];
            *(float4*)&b[0] = *(const float4*)&Bs[k][tx * 8];
            *(float4*)&b[4] = *(const float4*)&Bs[k][tx * 8 + 4];
            #pragma unroll
            for (int i = 0; i < 8; i++)
                #pragma unroll
                for (int j = 0; j < 8; j++)
                    acc[i][j] = fmaf(a[i], b[j], acc[i][j]);
        }
        __syncthreads();
    }

    // --- epilogue + store
    #pragma unroll
    for (int i = 0; i < 8; i++) {
        int gm = m0 + ty * 8 + i;
        if (gm < M) {
            #pragma unroll
            for (int j = 0; j < 8; j++) {
                int gn = n0 + tx * 8 + j;
                if (gn < N) {
                    float v = acc[i][j] * alpha;
                    if (EPI == 1) v += RES[(long)gm * ldc + gn];
                    if (EPI == 2) v = 0.5f * v * (1.0f + erff(v * 0.70710678118654752440f));
                    C[(long)gm * ldc + gn] = v;
                }
            }
        }
    }
}

// ---------------- host-side orchestration ----------------
static inline dim3 gemm_grid(int M, int N, int Z) {
    return dim3((N + 127) / 128, (M + 127) / 128, Z);
}

extern "C" void kernel_launch(void* const* d_in, const int* in_sizes, int n_in,
                              void* d_out, int out_size)
{
    const float* x     = (const float*)d_in[0];
    const float* mask  = (const float*)d_in[1];
    const float* wq    = (const float*)d_in[2];
    const float* wk    = (const float*)d_in[3];
    const float* wv    = (const float*)d_in[4];
    const float* wo    = (const float*)d_in[5];
    const float* w1    = (const float*)d_in[6];
    const float* w2    = (const float*)d_in[7];
    const float* ln1_w = (const float*)d_in[8];
    const float* ln1_b = (const float*)d_in[9];
    const float* ln2_w = (const float*)d_in[10];
    const float* ln2_b = (const float*)d_in[11];
    float* out = (float*)d_out;

    float *p_h, *p_q, *p_k, *p_v, *p_attn, *p_x1, *p_m, *p_sc;
    cudaGetSymbolAddress((void**)&p_h,    g_h);
    cudaGetSymbolAddress((void**)&p_q,    g_q);
    cudaGetSymbolAddress((void**)&p_k,    g_k);
    cudaGetSymbolAddress((void**)&p_v,    g_v);
    cudaGetSymbolAddress((void**)&p_attn, g_attn);
    cudaGetSymbolAddress((void**)&p_x1,   g_x1);
    cudaGetSymbolAddress((void**)&p_m,    g_m);
    cudaGetSymbolAddress((void**)&p_sc,   g_scores);

    const long SD  = (long)SS * DIM;      // per-batch stride of [B,S,DIM] tensors
    const long SS2 = (long)SS * SS;       // per-head stride of scores

    // 1) h = LN1(x)
    ln_kernel<<<TOK, 256>>>(x, ln1_w, ln1_b, p_h);

    // 2-4) q,k,v = h @ W{q,k,v}          [4096,1024] = [4096,1024]x[1024,1024]
    gemm_kernel<0,false><<<gemm_grid(TOK, DIM, 1), 256>>>(
        p_h, wq, p_q, nullptr, TOK, DIM, DIM, DIM, DIM, DIM,
        1, 0,0, 0,0, 0,0, 1.0f);
    gemm_kernel<0,false><<<gemm_grid(TOK, DIM, 1), 256>>>(
        p_h, wk, p_k, nullptr, TOK, DIM, DIM, DIM, DIM, DIM,
        1, 0,0, 0,0, 0,0, 1.0f);
    gemm_kernel<0,false><<<gemm_grid(TOK, DIM, 1), 256>>>(
        p_h, wv, p_v, nullptr, TOK, DIM, DIM, DIM, DIM, DIM,
        1, 0,0, 0,0, 0,0, 1.0f);

    // 5) scores = (Q_bh @ K_bh^T) / 8    per (b,h): [2048,2048] k=64
    gemm_kernel<0,true><<<gemm_grid(SS, SS, BB * HEADS), 256>>>(
        p_q, p_k, p_sc, nullptr, SS, SS, HEAD_DIM, DIM, DIM, SS,
        HEADS,
        SD, (long)HEAD_DIM,          // A = Q
        SD, (long)HEAD_DIM,          // B = K
        (long)HEADS * SS2, SS2,      // C = scores
        0.125f);

    // 6) softmax rows (mask added here; mask broadcast over b,h)
    softmax_kernel<<<BB * HEADS * SS, 256>>>(p_sc, mask);

    // 7) attn = probs @ V_bh             per (b,h): [2048,64] k=2048
    gemm_kernel<0,false><<<gemm_grid(SS, HEAD_DIM, BB * HEADS), 256>>>(
        p_sc, p_v, p_attn, nullptr, SS, HEAD_DIM, SS, SS, DIM, DIM,
        HEADS,
        (long)HEADS * SS2, SS2,      // A = probs
        SD, (long)HEAD_DIM,          // B = V
        SD, (long)HEAD_DIM,          // C = attn (strided into [B,S,DIM])
        1.0f);

    // 8) x1 = x + attn @ Wo
    gemm_kernel<1,false><<<gemm_grid(TOK, DIM, 1), 256>>>(
        p_attn, wo, p_x1, x, TOK, DIM, DIM, DIM, DIM, DIM,
        1, 0,0, 0,0, 0,0, 1.0f);

    // 9) h = LN2(x1)
    ln_kernel<<<TOK, 256>>>(p_x1, ln2_w, ln2_b, p_h);

    // 10) m = gelu(h @ W1)               [4096,4096]
    gemm_kernel<2,false><<<gemm_grid(TOK, FFN, 1), 256>>>(
        p_h, w1, p_m, nullptr, TOK, FFN, DIM, DIM, FFN, FFN,
        1, 0,0, 0,0, 0,0, 1.0f);

    // 11) out = x1 + m @ W2
    gemm_kernel<1,false><<<gemm_grid(TOK, DIM, 1), 256>>>(
        p_m, w2, out, p_x1, TOK, DIM, FFN, FFN, DIM, DIM,
        1, 0,0, 0,0, 0,0, 1.0f);
}

// round 15
// speedup vs baseline: 1.1692x; 1.1692x over previous
#include <cuda_runtime.h>
#include <cuda_bf16.h>
#include <math.h>
#include <stdint.h>

// ---------------- problem constants ----------------
#define BB 2
#define SS 2048
#define DIM 1024
#define HEADS 16
#define HEAD_DIM 64
#define FFN 4096
#define TOK (BB * SS)   // 4096 tokens

typedef __nv_bfloat16 bf16;

// tcgen05 is only legal in arch-specific (sm_103a) / family-specific passes.
#if defined(__CUDA_ARCH__) && (__CUDA_ARCH__ >= 1000) && \
    (defined(__CUDA_ARCH_FEAT_SM103_ALL) || defined(__CUDA_ARCH_FEAT_SM100_ALL) || \
     defined(__CUDA_ARCH_SPECIFIC__) || defined(__CUDA_ARCH_FAMILY_SPECIFIC__))
#define TC_OK 1
#else
#define TC_OK 0
#endif

// ---------------- scratch (device globals; no allocations allowed) ----------
__device__ __align__(1024) bf16 g_hhi[TOK * DIM];
__device__ __align__(1024) bf16 g_hlo[TOK * DIM];
__device__ __align__(1024) bf16 g_qhi[TOK * DIM];
__device__ __align__(1024) bf16 g_qlo[TOK * DIM];
__device__ __align__(1024) bf16 g_khi[TOK * DIM];
__device__ __align__(1024) bf16 g_klo[TOK * DIM];
__device__ __align__(1024) bf16 g_vthi[BB * DIM * SS];   // [b][d][t]
__device__ __align__(1024) bf16 g_vtlo[BB * DIM * SS];
__device__ __align__(1024) bf16 g_attnhi[TOK * DIM];
__device__ __align__(1024) bf16 g_attnlo[TOK * DIM];
__device__ __align__(1024) bf16 g_mhi[TOK * FFN];
__device__ __align__(1024) bf16 g_mlo[TOK * FFN];
__device__ __align__(1024) float g_x1[TOK * DIM];
__device__ __align__(1024) float g_scores[(size_t)BB * HEADS * SS * SS]; // 537MB
__device__ __align__(1024) bf16  g_phi[(size_t)BB * HEADS * SS * SS];
__device__ __align__(1024) bf16  g_plo[(size_t)BB * HEADS * SS * SS];
// transposed+converted weights: T[n][k]
__device__ __align__(1024) bf16 g_wqthi[DIM * DIM], g_wqtlo[DIM * DIM];
__device__ __align__(1024) bf16 g_wkthi[DIM * DIM], g_wktlo[DIM * DIM];
__device__ __align__(1024) bf16 g_wvthi[DIM * DIM], g_wvtlo[DIM * DIM];
__device__ __align__(1024) bf16 g_wothi[DIM * DIM], g_wotlo[DIM * DIM];
__device__ __align__(1024) bf16 g_w1thi[FFN * DIM], g_w1tlo[FFN * DIM];
__device__ __align__(1024) bf16 g_w2thi[DIM * FFN], g_w2tlo[DIM * FFN];

// ---------------- small helpers ----------------
__device__ __forceinline__ uint32_t smem_u32(const void* p) {
    uint32_t a;
    asm("{ .reg .u64 t; cvta.to.shared.u64 t, %1; cvt.u32.u64 %0, t; }"
        : "=r"(a) : "l"(p));
    return a;
}
__device__ __forceinline__ void split2(float v, bf16& h, bf16& l) {
    h = __float2bfloat16(v);
    l = __float2bfloat16(v - __bfloat162float(h));
}
__device__ __forceinline__ float b2f(bf16 v) { return __bfloat162float(v); }

#if TC_OK
__device__ __forceinline__ uint32_t elect1() {
    uint32_t p;
    asm volatile("{\n\t.reg .pred P;\n\telect.sync _|P, 0xFFFFFFFF;\n\t"
                 "selp.b32 %0, 1, 0, P;\n\t}" : "=r"(p));
    return p;
}
__device__ __forceinline__ void mbar_init(uint32_t mbar, uint32_t cnt) {
    asm volatile("mbarrier.init.shared.b64 [%0], %1;" :: "r"(mbar), "r"(cnt) : "memory");
}
__device__ __forceinline__ void mbar_inval(uint32_t mbar) {
    asm volatile("mbarrier.inval.shared.b64 [%0];" :: "r"(mbar) : "memory");
}
// Bounded wait on parity 0: clock64 budget (~1M cycles ≈ 0.5ms). Small
// suspend hint (1us) so a lost commit costs at most the budget, keeping the
// whole run far under the harness timeout even if EVERY wait fails.
__device__ __forceinline__ uint32_t mbar_wait_bounded(uint32_t mbar) {
    unsigned long long t0 = clock64();
    do {
        uint32_t done;
        asm volatile(
            "{\n\t.reg .pred P;\n\t"
            "mbarrier.try_wait.parity.acquire.cta.shared::cta.b64 P, [%1], %2, 1000;\n\t"
            "selp.b32 %0, 1, 0, P;\n\t}"
            : "=r"(done) : "r"(mbar), "r"(0u) : "memory");
        if (done) return 1u;
    } while (clock64() - t0 < 1000000ULL);
    return 0u;
}
__device__ __forceinline__ uint64_t mk_desc(uint32_t addr) {
    const uint64_t BASE = (2ull << 61) | (1ull << 46) | (64ull << 32) | (1ull << 16); // SW128, LBO=1, SBO=64
    return BASE | ((uint64_t)(addr >> 4) & 0x3FFF);
}
__device__ __forceinline__ void mma_f16_ss(uint32_t d, uint64_t a, uint64_t b,
                                           uint32_t idesc, uint32_t en) {
    asm volatile(
        "{\n\t.reg .pred p;\n\tsetp.ne.u32 p, %5, 0;\n\t"
        "tcgen05.mma.cta_group::1.kind::f16 [%0], %1, %2, %3, {%4,%4,%4,%4}, p;\n\t}"
        :: "r"(d), "l"(a), "l"(b), "r"(idesc), "r"(0u), "r"(en) : "memory");
}

#define TC_LD_X32(r, addr) \
    asm volatile( \
        "tcgen05.ld.sync.aligned.32x32b.x32.b32 " \
        "{%0, %1, %2, %3, %4, %5, %6, %7, " \
        " %8, %9, %10, %11, %12, %13, %14, %15, " \
        " %16, %17, %18, %19, %20, %21, %22, %23, " \
        " %24, %25, %26, %27, %28, %29, %30, %31}, [%32];" \
        : "=r"((r)[0]),  "=r"((r)[1]),  "=r"((r)[2]),  "=r"((r)[3]), \
          "=r"((r)[4]),  "=r"((r)[5]),  "=r"((r)[6]),  "=r"((r)[7]), \
          "=r"((r)[8]),  "=r"((r)[9]),  "=r"((r)[10]), "=r"((r)[11]), \
          "=r"((r)[12]), "=r"((r)[13]), "=r"((r)[14]), "=r"((r)[15]), \
          "=r"((r)[16]), "=r"((r)[17]), "=r"((r)[18]), "=r"((r)[19]), \
          "=r"((r)[20]), "=r"((r)[21]), "=r"((r)[22]), "=r"((r)[23]), \
          "=r"((r)[24]), "=r"((r)[25]), "=r"((r)[26]), "=r"((r)[27]), \
          "=r"((r)[28]), "=r"((r)[29]), "=r"((r)[30]), "=r"((r)[31]) \
        : "r"(addr))
#endif // TC_OK

// ---------------- shared epilogue ----------------
// EPI: 0=split(Chi/Clo)  1=fp32 (Cf)  2=fp32+RES(Cf)  3=gelu->split  4=V-transpose split
template<int EPI>
__device__ __forceinline__ void epi_store(float v, int gm, int gn, long coff, long ldc,
                                          bf16* Chi, bf16* Clo, float* Cf,
                                          const float* RES)
{
    if (EPI == 0) {
        bf16 h, l; split2(v, h, l);
        long idx = coff + (long)gm * ldc + gn;
        Chi[idx] = h; Clo[idx] = l;
    } else if (EPI == 1) {
        Cf[coff + (long)gm * ldc + gn] = v;
    } else if (EPI == 2) {
        long idx = coff + (long)gm * ldc + gn;
        Cf[idx] = v + RES[idx];
    } else if (EPI == 3) {
        float g = 0.5f * v * (1.0f + erff(v * 0.70710678118654752440f));
        bf16 h, l; split2(g, h, l);
        long idx = coff + (long)gm * ldc + gn;
        Chi[idx] = h; Clo[idx] = l;
    } else {  // EPI 4: V-transpose: vt[b][d][t]
        long idx = ((long)(gm >> 11) * DIM + gn) * SS + (gm & (SS - 1));
        bf16 h, l; split2(v, h, l);
        Chi[idx] = h; Clo[idx] = l;
    }
}

// ---------------- proven FFMA tile (R1-style), used as fallback / generic ---
template<int NT, int EPI>
__device__ void ffma_tile(const bf16* __restrict__ Ahi, const bf16* __restrict__ Alo,
                          long lda,
                          const bf16* __restrict__ Bhi, const bf16* __restrict__ Blo,
                          long ldb,
                          bf16* Chi, bf16* Clo, float* Cf, const float* RES, long ldc,
                          int K, float alpha, long coff, int m0, int n0)
{
    constexpr int CW = NT / 16;               // cols per thread
    __shared__ float As[16][132];
    __shared__ float Bs[16][NT + 4];

    const int tid = threadIdx.x;
    const int tx = tid & 15;
    const int ty = tid >> 4;

    float acc[8][CW] = {};

    for (int k0 = 0; k0 < K; k0 += 16) {
        #pragma unroll
        for (int it = 0; it < 8; it++) {
            int idx = tid + it * 256;         // 2048 = 128 x 16
            int m = idx >> 4, k = idx & 15;
            long off = (long)m * lda + k0 + k;
            As[k][m] = b2f(Ahi[off]) + b2f(Alo[off]);
        }
        for (int idx = tid; idx < NT * 16; idx += 256) {
            int n = idx >> 4, k = idx & 15;
            long off = (long)n * ldb + k0 + k;
            Bs[k][n] = b2f(Bhi[off]) + b2f(Blo[off]);
        }
        __syncthreads();
        #pragma unroll
        for (int k = 0; k < 16; k++) {
            float a[8], b[CW];
            #pragma unroll
            for (int i = 0; i < 8; i++) a[i] = As[k][ty * 8 + i];
            #pragma unroll
            for (int j = 0; j < CW; j++) b[j] = Bs[k][tx * CW + j];
            #pragma unroll
            for (int i = 0; i < 8; i++)
                #pragma unroll
                for (int j = 0; j < CW; j++)
                    acc[i][j] = fmaf(a[i], b[j], acc[i][j]);
        }
        __syncthreads();
    }

    #pragma unroll
    for (int i = 0; i < 8; i++) {
        int gm = m0 + ty * 8 + i;
        #pragma unroll
        for (int j = 0; j < CW; j++) {
            int gn = n0 + tx * CW + j;
            epi_store<EPI>(acc[i][j] * alpha, gm, gn, coff, ldc, Chi, Clo, Cf, RES);
        }
    }
}

// ---------------- LayerNorm: fp32 in -> bf16 hi/lo out ----------------
__global__ __launch_bounds__(256)
void ln_kernel(const float* __restrict__ X, const float* __restrict__ W,
               const float* __restrict__ Bv, bf16* __restrict__ Yhi,
               bf16* __restrict__ Ylo)
{
    long row = blockIdx.x;
    const float* x = X + row * DIM;
    __shared__ float sm[DIM];
    __shared__ float red[256];
    int tid = threadIdx.x;

    float s = 0.f;
    for (int i = tid; i < DIM; i += 256) { float v = x[i]; sm[i] = v; s += v; }
    red[tid] = s; __syncthreads();
    for (int o = 128; o > 0; o >>= 1) { if (tid < o) red[tid] += red[tid + o]; __syncthreads(); }
    float mean = red[0] * (1.0f / DIM);
    __syncthreads();

    float s2 = 0.f;
    for (int i = tid; i < DIM; i += 256) { float d = sm[i] - mean; s2 += d * d; }
    red[tid] = s2; __syncthreads();
    for (int o = 128; o > 0; o >>= 1) { if (tid < o) red[tid] += red[tid + o]; __syncthreads(); }
    float var = red[0] * (1.0f / DIM);
    float inv = rsqrtf(var + 1e-12f);

    for (int i = tid; i < DIM; i += 256) {
        float v = W[i] * ((sm[i] - mean) * inv) + Bv[i];
        bf16 h, l; split2(v, h, l);
        Yhi[row * DIM + i] = h;
        Ylo[row * DIM + i] = l;
    }
}

// ---------------- Softmax: fp32 scores (+mask) -> bf16 hi/lo probs ----------
__global__ __launch_bounds__(256)
void softmax_kernel(const float* __restrict__ S, const float* __restrict__ mask,
                    bf16* __restrict__ Phi, bf16* __restrict__ Plo)
{
    long row = blockIdx.x;                 // 0 .. B*H*S-1
    int srow = (int)(row % SS);
    const float* p = S + row * (long)SS;
    const float* mrow = mask + (long)srow * SS;
    __shared__ float sm[SS];
    __shared__ float red[256];
    int tid = threadIdx.x;

    float mx = -INFINITY;
    for (int i = tid; i < SS; i += 256) {
        float v = p[i] + mrow[i];
        sm[i] = v;
        mx = fmaxf(mx, v);
    }
    red[tid] = mx; __syncthreads();
    for (int o = 128; o > 0; o >>= 1) { if (tid < o) red[tid] = fmaxf(red[tid], red[tid + o]); __syncthreads(); }
    mx = red[0]; __syncthreads();

    float s = 0.f;
    for (int i = tid; i < SS; i += 256) {
        float e = __expf(sm[i] - mx);
        sm[i] = e;
        s += e;
    }
    red[tid] = s; __syncthreads();
    for (int o = 128; o > 0; o >>= 1) { if (tid < o) red[tid] += red[tid + o]; __syncthreads(); }
    float inv = 1.0f / red[0];

    for (int i = tid; i < SS; i += 256) {
        float v = sm[i] * inv;
        bf16 h, l; split2(v, h, l);
        Phi[row * (long)SS + i] = h;
        Plo[row * (long)SS + i] = l;
    }
}

// ---------------- transpose + hi/lo convert:  W[K][N] -> T[n][k] ------------
__global__ __launch_bounds__(256)
void tconv_kernel(const float* __restrict__ W, bf16* __restrict__ Thi,
                  bf16* __restrict__ Tlo, int Kd, int Nd)
{
    __shared__ float t[32][33];
    int k0 = blockIdx.y * 32, n0 = blockIdx.x * 32;
    int tx = threadIdx.x, ty = threadIdx.y;   // (32, 8)
    #pragma unroll
    for (int i = 0; i < 4; i++)
        t[ty + i * 8][tx] = W[(long)(k0 + ty + i * 8) * Nd + n0 + tx];
    __syncthreads();
    #pragma unroll
    for (int i = 0; i < 4; i++) {
        int n = n0 + ty + i * 8, k = k0 + tx;
        float v = t[tx][ty + i * 8];
        bf16 h, l; split2(v, h, l);
        Thi[(long)n * Kd + k] = h;
        Tlo[(long)n * Kd + k] = l;
    }
}

// ---------------- GEMM: D[m][n] = sum_k A[m][k]*B[n][k] ---------------------
// Self-healing: tcgen05 fast path + per-CTA spot-check; on any anomaly the CTA
// recomputes its tile with the proven FFMA loop. Generic pass: FFMA only.
template<int NT, int EPI>
__global__ void __launch_bounds__(256, 1) __cluster_dims__(1, 1, 1)
gemm_tc(const bf16* __restrict__ Ahi, const bf16* __restrict__ Alo, long lda,
        const bf16* __restrict__ Bhi, const bf16* __restrict__ Blo, long ldb,
        bf16* __restrict__ Chi, bf16* __restrict__ Clo,
        float* __restrict__ Cf, const float* __restrict__ RES, long ldc,
        int K, float alpha, int Hb,
        long bsA, long hsA, long bsB, long hsB, long bsC, long hsC)
{
    const int tid = threadIdx.x;

    const int z = blockIdx.z, zb = z / Hb, zh = z % Hb;
    Ahi += zb * bsA + zh * hsA;  Alo += zb * bsA + zh * hsA;
    Bhi += zb * bsB + zh * hsB;  Blo += zb * bsB + zh * hsB;
    const long coff = zb * bsC + zh * hsC;

    const int m0 = blockIdx.y * 128;
    const int n0 = blockIdx.x * NT;
    Ahi += (long)m0 * lda;  Alo += (long)m0 * lda;
    Bhi += (long)n0 * ldb;  Blo += (long)n0 * ldb;

#if TC_OK
    extern __shared__ char smem[];
    const uint32_t sb = smem_u32(smem);
    const int wid = tid >> 5;
    const int lane = tid & 31;
    __shared__ int s_bad;

    constexpr uint32_t IDESC =
        (1u << 4) | (1u << 7) | (1u << 10) | ((uint32_t)(NT / 8) << 17) | (8u << 24);
    const uint32_t mb = sb + 16;
    const uint32_t stage = (sb + 1024 + 1023) & ~1023u;   // 1024-aligned for SW128

    if (wid == 0) {
        asm volatile("tcgen05.alloc.cta_group::1.sync.aligned.shared::cta.b32 [%0], %1;"
                     :: "r"(sb), "r"((uint32_t)NT) : "memory");
        asm volatile("tcgen05.relinquish_alloc_permit.cta_group::1.sync.aligned;"
                     ::: "memory");
    }
    if (tid == 0) { mbar_init(mb, 1); s_bad = 0; }
    __syncthreads();
    uint32_t tmem;
    asm volatile("ld.shared.b32 %0, [%1];" : "=r"(tmem) : "r"(sb));

    const int C = K >> 6;   // chunks of 64
    int alive = 1;

    for (int c = 0; c < C; c++) {
        if (c > 0 && tid == 0) { mbar_inval(mb); mbar_init(mb, 1); }
        __syncthreads();

        // ---- stage loader: LDG.128 -> swizzled STS.128 (single stage) ----
        #pragma unroll
        for (int i = tid; i < 2048; i += 256) {        // A hi (1024 16B units) + lo
            int half = i >> 10;
            int j = i & 1023;
            int r = j >> 3, u = j & 7;
            const bf16* src = (half ? Alo : Ahi) + (long)r * lda + c * 64 + u * 8;
            uint4 val = *reinterpret_cast<const uint4*>(src);
            uint32_t dst = stage + (half << 14) + r * 128 + ((u ^ (r & 7)) << 4);
            asm volatile("st.shared.v4.b32 [%0], {%1,%2,%3,%4};"
                         :: "r"(dst), "r"(val.x), "r"(val.y), "r"(val.z), "r"(val.w));
        }
        #pragma unroll
        for (int i = tid; i < NT * 16; i += 256) {     // B hi + lo
            int half = (i >= NT * 8);
            int j = half ? i - NT * 8 : i;
            int r = j >> 3, u = j & 7;
            const bf16* src = (half ? Blo : Bhi) + (long)r * ldb + c * 64 + u * 8;
            uint4 val = *reinterpret_cast<const uint4*>(src);
            uint32_t dst = stage + 32768 + half * (NT * 128) + r * 128 + ((u ^ (r & 7)) << 4);
            asm volatile("st.shared.v4.b32 [%0], {%1,%2,%3,%4};"
                         :: "r"(dst), "r"(val.x), "r"(val.y), "r"(val.z), "r"(val.w));
        }
        asm volatile("tcgen05.fence::before_thread_sync;" ::: "memory");
        __syncthreads();

        if (wid == 0) {
            asm volatile("tcgen05.fence::after_thread_sync;" ::: "memory");
            if (elect1()) {
                uint64_t dAh = mk_desc(stage);
                uint64_t dAl = mk_desc(stage + 16384);
                uint64_t dBh = mk_desc(stage + 32768);
                uint64_t dBl = mk_desc(stage + 32768 + NT * 128);
                #pragma unroll
                for (int ks = 0; ks < 4; ks++)
                    mma_f16_ss(tmem, dAh + ks * 2, dBh + ks * 2, IDESC,
                               (c == 0 && ks == 0) ? 0u : 1u);
                #pragma unroll
                for (int ks = 0; ks < 4; ks++)
                    mma_f16_ss(tmem, dAh + ks * 2, dBl + ks * 2, IDESC, 1u);
                #pragma unroll
                for (int ks = 0; ks < 4; ks++)
                    mma_f16_ss(tmem, dAl + ks * 2, dBh + ks * 2, IDESC, 1u);
                asm volatile(
                    "tcgen05.commit.cta_group::1.mbarrier::arrive::one.shared::cluster.b64 [%0];"
                    :: "r"(mb) : "memory");
            }
        }
        int got = (int)mbar_wait_bounded(mb);
        alive = __syncthreads_and(got);        // uniform verdict + barrier
        if (!alive) break;                     // uniform break -> fallback
    }
    asm volatile("tcgen05.fence::after_thread_sync;" ::: "memory");

    // ---- read accumulator + spot-check ----
    uint32_t rall[NT / 32 * 32];
    if (tid < 128) {
        #pragma unroll
        for (int cc = 0; cc < NT / 32; cc++) {
            TC_LD_X32(rall + cc * 32, tmem + cc * 32);
        }
        asm volatile("tcgen05.wait::ld.sync.aligned;" ::: "memory");
        asm volatile("tcgen05.fence::before_thread_sync;" ::: "memory");

        // warp w verifies element (row = 32w + w, col = w), w = 0..3
        int mloc = 32 * wid + wid;
        int nloc = wid;
        float s = 0.f;
        for (int k = lane; k < K; k += 32) {
            float a = b2f(Ahi[(long)mloc * lda + k]) + b2f(Alo[(long)mloc * lda + k]);
            float b = b2f(Bhi[(long)nloc * ldb + k]) + b2f(Blo[(long)nloc * ldb + k]);
            s = fmaf(a, b, s);
        }
        #pragma unroll
        for (int o = 16; o > 0; o >>= 1) s += __shfl_xor_sync(0xFFFFFFFFu, s, o);
        if (lane == wid) {   // this lane holds row 32w+w; column w is rall[w]
            float tc = __uint_as_float(rall[wid]);
            int bad = (!alive) || (!isfinite(tc)) ||
                      (fabsf(tc - s) > 0.02f + 0.02f * fabsf(s));
            if (bad) s_bad = 1;
        }
    }
    __syncthreads();

    if (!s_bad) {
        if (tid < 128) {
            int gm = m0 + tid;
            #pragma unroll
            for (int cc = 0; cc < NT / 32; cc++) {
                #pragma unroll
                for (int j = 0; j < 32; j++) {
                    int gn = n0 + cc * 32 + j;
                    float v = __uint_as_float(rall[cc * 32 + j]) * alpha;
                    epi_store<EPI>(v, gm, gn, coff, ldc, Chi, Clo, Cf, RES);
                }
            }
        }
    } else {
        // self-heal: recompute this tile with the proven FFMA loop
        ffma_tile<NT, EPI>(Ahi, Alo, lda, Bhi, Blo, ldb,
                           Chi, Clo, Cf, RES, ldc, K, alpha, coff, m0, n0);
    }

    __syncthreads();
    if (tid == 0) mbar_inval(mb);
    if (wid == 0) {
        asm volatile("tcgen05.dealloc.cta_group::1.sync.aligned.b32 %0, %1;"
                     :: "r"(tmem), "r"((uint32_t)NT));
    }
#else
    ffma_tile<NT, EPI>(Ahi, Alo, lda, Bhi, Blo, ldb,
                       Chi, Clo, Cf, RES, ldc, K, alpha, coff, m0, n0);
#endif
}

// ---------------- host-side orchestration ----------------
// dyn smem: 1024 hdr + up to 1024 align slack + A(32K) + B(NT*256)
#define SMEM_DYN64 (2048 + 32768 + 64 * 256)    // 53248

extern "C" void kernel_launch(void* const* d_in, const int* in_sizes, int n_in,
                              void* d_out, int out_size)
{
    const float* x     = (const float*)d_in[0];
    const float* mask  = (const float*)d_in[1];
    const float* wq    = (const float*)d_in[2];
    const float* wk    = (const float*)d_in[3];
    const float* wv    = (const float*)d_in[4];
    const float* wo    = (const float*)d_in[5];
    const float* w1    = (const float*)d_in[6];
    const float* w2    = (const float*)d_in[7];
    const float* ln1_w = (const float*)d_in[8];
    const float* ln1_b = (const float*)d_in[9];
    const float* ln2_w = (const float*)d_in[10];
    const float* ln2_b = (const float*)d_in[11];
    float* out = (float*)d_out;

    cudaFuncSetAttribute(gemm_tc<64,0>, cudaFuncAttributeMaxDynamicSharedMemorySize, SMEM_DYN64);
    cudaFuncSetAttribute(gemm_tc<64,1>, cudaFuncAttributeMaxDynamicSharedMemorySize, SMEM_DYN64);
    cudaFuncSetAttribute(gemm_tc<64,2>, cudaFuncAttributeMaxDynamicSharedMemorySize, SMEM_DYN64);
    cudaFuncSetAttribute(gemm_tc<64,3>, cudaFuncAttributeMaxDynamicSharedMemorySize, SMEM_DYN64);
    cudaFuncSetAttribute(gemm_tc<64,4>, cudaFuncAttributeMaxDynamicSharedMemorySize, SMEM_DYN64);

    bf16 *hhi, *hlo, *qhi, *qlo, *khi, *klo, *vthi, *vtlo, *athi, *atlo, *mhi, *mlo;
    bf16 *phi, *plo;
    bf16 *wqth, *wqtl, *wkth, *wktl, *wvth, *wvtl, *woth, *wotl, *w1th, *w1tl, *w2th, *w2tl;
    float *x1, *sc;
    cudaGetSymbolAddress((void**)&hhi, g_hhi);   cudaGetSymbolAddress((void**)&hlo, g_hlo);
    cudaGetSymbolAddress((void**)&qhi, g_qhi);   cudaGetSymbolAddress((void**)&qlo, g_qlo);
    cudaGetSymbolAddress((void**)&khi, g_khi);   cudaGetSymbolAddress((void**)&klo, g_klo);
    cudaGetSymbolAddress((void**)&vthi, g_vthi); cudaGetSymbolAddress((void**)&vtlo, g_vtlo);
    cudaGetSymbolAddress((void**)&athi, g_attnhi); cudaGetSymbolAddress((void**)&atlo, g_attnlo);
    cudaGetSymbolAddress((void**)&mhi, g_mhi);   cudaGetSymbolAddress((void**)&mlo, g_mlo);
    cudaGetSymbolAddress((void**)&phi, g_phi);   cudaGetSymbolAddress((void**)&plo, g_plo);
    cudaGetSymbolAddress((void**)&x1, g_x1);     cudaGetSymbolAddress((void**)&sc, g_scores);
    cudaGetSymbolAddress((void**)&wqth, g_wqthi); cudaGetSymbolAddress((void**)&wqtl, g_wqtlo);
    cudaGetSymbolAddress((void**)&wkth, g_wkthi); cudaGetSymbolAddress((void**)&wktl, g_wktlo);
    cudaGetSymbolAddress((void**)&wvth, g_wvthi); cudaGetSymbolAddress((void**)&wvtl, g_wvtlo);
    cudaGetSymbolAddress((void**)&woth, g_wothi); cudaGetSymbolAddress((void**)&wotl, g_wotlo);
    cudaGetSymbolAddress((void**)&w1th, g_w1thi); cudaGetSymbolAddress((void**)&w1tl, g_w1tlo);
    cudaGetSymbolAddress((void**)&w2th, g_w2thi); cudaGetSymbolAddress((void**)&w2tl, g_w2tlo);

    const long SD  = (long)SS * DIM;
    const long SS2 = (long)SS * SS;
    dim3 tb(32, 8);

    // ---- weight transpose+convert ----
    tconv_kernel<<<dim3(DIM/32, DIM/32), tb>>>(wq, wqth, wqtl, DIM, DIM);
    tconv_kernel<<<dim3(DIM/32, DIM/32), tb>>>(wk, wkth, wktl, DIM, DIM);
    tconv_kernel<<<dim3(DIM/32, DIM/32), tb>>>(wv, wvth, wvtl, DIM, DIM);
    tconv_kernel<<<dim3(DIM/32, DIM/32), tb>>>(wo, woth, wotl, DIM, DIM);
    tconv_kernel<<<dim3(FFN/32, DIM/32), tb>>>(w1, w1th, w1tl, DIM, FFN);
    tconv_kernel<<<dim3(DIM/32, FFN/32), tb>>>(w2, w2th, w2tl, FFN, DIM);

    // ---- 1) h = LN1(x) ----
    ln_kernel<<<TOK, 256>>>(x, ln1_w, ln1_b, hhi, hlo);

    // ---- 2) q, k (split epilogue), v (transposed split epilogue) ----
    gemm_tc<64,0><<<dim3(DIM/64, TOK/128, 1), 256, SMEM_DYN64>>>(
        hhi, hlo, DIM, wqth, wqtl, DIM, qhi, qlo, nullptr, nullptr, DIM,
        DIM, 1.0f, 1, 0,0, 0,0, 0,0);
    gemm_tc<64,0><<<dim3(DIM/64, TOK/128, 1), 256, SMEM_DYN64>>>(
        hhi, hlo, DIM, wkth, wktl, DIM, khi, klo, nullptr, nullptr, DIM,
        DIM, 1.0f, 1, 0,0, 0,0, 0,0);
    gemm_tc<64,4><<<dim3(DIM/64, TOK/128, 1), 256, SMEM_DYN64>>>(
        hhi, hlo, DIM, wvth, wvtl, DIM, vthi, vtlo, nullptr, nullptr, DIM,
        DIM, 1.0f, 1, 0,0, 0,0, 0,0);

    // ---- 3) scores = (Q K^T)/8 per (b,h): M=2048 N=2048 K=64 ----
    gemm_tc<64,1><<<dim3(SS/64, SS/128, BB*HEADS), 256, SMEM_DYN64>>>(
        qhi, qlo, DIM, khi, klo, DIM, nullptr, nullptr, sc, nullptr, SS,
        HEAD_DIM, 0.125f, HEADS,
        SD, (long)HEAD_DIM, SD, (long)HEAD_DIM,
        (long)HEADS * SS2, SS2);

    // ---- 4) softmax -> probs hi/lo ----
    softmax_kernel<<<BB*HEADS*SS, 256>>>(sc, mask, phi, plo);

    // ---- 5) attn = probs @ V per (b,h): M=2048 N=64 K=2048 ----
    gemm_tc<64,0><<<dim3(1, SS/128, BB*HEADS), 256, SMEM_DYN64>>>(
        phi, plo, SS, vthi, vtlo, SS, athi, atlo, nullptr, nullptr, DIM,
        SS, 1.0f, HEADS,
        (long)HEADS * SS2, SS2,
        (long)DIM * SS, (long)HEAD_DIM * SS,
        SD, (long)HEAD_DIM);

    // ---- 6) x1 = x + attn @ Wo ----
    gemm_tc<64,2><<<dim3(DIM/64, TOK/128, 1), 256, SMEM_DYN64>>>(
        athi, atlo, DIM, woth, wotl, DIM, nullptr, nullptr, x1, x, DIM,
        DIM, 1.0f, 1, 0,0, 0,0, 0,0);

    // ---- 7) h2 = LN2(x1) ----
    ln_kernel<<<TOK, 256>>>(x1, ln2_w, ln2_b, hhi, hlo);

    // ---- 8) m = gelu(h2 @ W1) ----
    gemm_tc<64,3><<<dim3(FFN/64, TOK/128, 1), 256, SMEM_DYN64>>>(
        hhi, hlo, DIM, w1th, w1tl, DIM, mhi, mlo, nullptr, nullptr, FFN,
        DIM, 1.0f, 1, 0,0, 0,0, 0,0);

    // ---- 9) out = x1 + m @ W2 ----
    gemm_tc<64,2><<<dim3(DIM/64, TOK/128, 1), 256, SMEM_DYN64>>>(
        mhi, mlo, FFN, w2th, w2tl, FFN, nullptr, nullptr, out, x1, DIM,
        FFN, 1.0f, 1, 0,0, 0,0, 0,0);
}